// round 1
// baseline (speedup 1.0000x reference)
#include <cuda_runtime.h>
#include <cuda_bf16.h>
#include <cstddef>

// Problem constants
#define BB   8
#define NN   1024
#define CC   768
#define HH   12
#define DH   64
#define CQKV 2304            // 3*C
#define MROWS (BB*NN)        // 8192

// Scratch (device globals: allocation-free per harness rules)
__device__ float g_qkv[(size_t)MROWS * CQKV];   // (8192, 2304)
__device__ float g_att[(size_t)MROWS * CC];     // (8192, 768)

// ---------------------------------------------------------------------------
// Tiled SGEMM: C = A(MxK) @ B(KxN) [+ bias], row-major, M%128==0, N%128==0, K%16==0
// ---------------------------------------------------------------------------
__global__ __launch_bounds__(256)
void sgemm128(const float* __restrict__ A, const float* __restrict__ B,
              const float* __restrict__ bias, float* __restrict__ C,
              int M, int N, int K)
{
    constexpr int BM = 128, BN = 128, BK = 16;
    __shared__ __align__(16) float As[BK][BM + 4];   // transposed A tile, padded
    __shared__ float4 Bs[BK][BN / 4];

    const int tid = threadIdx.x;
    const int tx  = tid & 15;        // n direction (x8)
    const int ty  = tid >> 4;        // m direction (x8)
    const int m0  = blockIdx.y * BM;
    const int n0  = blockIdx.x * BN;

    float acc[8][8];
    #pragma unroll
    for (int i = 0; i < 8; i++)
        #pragma unroll
        for (int j = 0; j < 8; j++) acc[i][j] = 0.f;

    for (int k0 = 0; k0 < K; k0 += BK) {
        // Load A tile (BM x BK), store transposed into As
        #pragma unroll
        for (int i = 0; i < 2; i++) {
            int idx = tid + i * 256;          // 512 float4 total
            int row = idx >> 2;
            int c4  = (idx & 3) * 4;
            float4 a = *(const float4*)&A[(size_t)(m0 + row) * K + k0 + c4];
            As[c4 + 0][row] = a.x;
            As[c4 + 1][row] = a.y;
            As[c4 + 2][row] = a.z;
            As[c4 + 3][row] = a.w;
        }
        // Load B tile (BK x BN)
        #pragma unroll
        for (int i = 0; i < 2; i++) {
            int idx = tid + i * 256;          // 512 float4 total
            int row = idx >> 5;
            int c4  = idx & 31;
            Bs[row][c4] = *(const float4*)&B[(size_t)(k0 + row) * N + n0 + c4 * 4];
        }
        __syncthreads();

        #pragma unroll
        for (int k = 0; k < BK; k++) {
            float a[8], b[8];
            *(float4*)&a[0] = *(const float4*)&As[k][ty * 8];
            *(float4*)&a[4] = *(const float4*)&As[k][ty * 8 + 4];
            *(float4*)&b[0] = Bs[k][tx * 2];
            *(float4*)&b[4] = Bs[k][tx * 2 + 1];
            #pragma unroll
            for (int i = 0; i < 8; i++)
                #pragma unroll
                for (int j = 0; j < 8; j++)
                    acc[i][j] += a[i] * b[j];
        }
        __syncthreads();
    }

    // Epilogue (+ optional bias)
    #pragma unroll
    for (int i = 0; i < 8; i++) {
        float* crow = &C[(size_t)(m0 + ty * 8 + i) * N + n0 + tx * 8];
        float4 o0 = make_float4(acc[i][0], acc[i][1], acc[i][2], acc[i][3]);
        float4 o1 = make_float4(acc[i][4], acc[i][5], acc[i][6], acc[i][7]);
        if (bias) {
            const float* bp = &bias[n0 + tx * 8];
            o0.x += bp[0]; o0.y += bp[1]; o0.z += bp[2]; o0.w += bp[3];
            o1.x += bp[4]; o1.y += bp[5]; o1.z += bp[6]; o1.w += bp[7];
        }
        *(float4*)&crow[0] = o0;
        *(float4*)&crow[4] = o1;
    }
}

// ---------------------------------------------------------------------------
// Streaming attention (no-max softmax: scores bounded |s|<~12, exp safe in fp32)
// grid = (N/128 qtiles, H, B), block = 128 threads, 1 query row / thread
// ---------------------------------------------------------------------------
__global__ __launch_bounds__(128)
void attn_kernel(const float* __restrict__ qkv, const int* __restrict__ mask,
                 float* __restrict__ out)
{
    constexpr int KT = 64;                    // keys per tile
    __shared__ float4 sbuf[2048];             // 32 KB: Q staging, then K(1024)+V(1024)
    __shared__ int    ms[KT];

    const int t  = threadIdx.x;
    const int q0 = blockIdx.x * 128;
    const int h  = blockIdx.y;
    const int b  = blockIdx.z;
    const float scale = 0.125f;               // 1/sqrt(64)

    const size_t rowbase = (size_t)b * NN;

    // ---- Stage Q tile (128 x 64) coalesced, then pull own row into registers
    #pragma unroll
    for (int i = 0; i < 16; i++) {
        int idx = i * 128 + t;                // 2048 float4
        int row = idx >> 4, c4 = idx & 15;
        sbuf[idx] = *(const float4*)&qkv[(rowbase + q0 + row) * CQKV + h * DH + c4 * 4];
    }
    __syncthreads();

    float q[64];
    #pragma unroll
    for (int c4 = 0; c4 < 16; c4++) {
        float4 v = sbuf[t * 16 + c4];
        q[c4 * 4 + 0] = v.x * scale;
        q[c4 * 4 + 1] = v.y * scale;
        q[c4 * 4 + 2] = v.z * scale;
        q[c4 * 4 + 3] = v.w * scale;
    }

    float acc[64];
    #pragma unroll
    for (int d = 0; d < 64; d++) acc[d] = 0.f;
    float l = 0.f;

    float4* Ks = sbuf;
    float4* Vs = sbuf + 1024;

    for (int jt = 0; jt < NN / KT; jt++) {
        const int j0 = jt * KT;
        __syncthreads();
        // Load K,V tiles (64 x 64 each) coalesced
        #pragma unroll
        for (int i = 0; i < 8; i++) {
            int idx = i * 128 + t;            // 1024 float4
            int row = idx >> 4, c4 = idx & 15;
            size_t base = (rowbase + j0 + row) * CQKV + h * DH + c4 * 4;
            Ks[idx] = *(const float4*)&qkv[base + CC];        // K at col offset 768
            Vs[idx] = *(const float4*)&qkv[base + 2 * CC];    // V at col offset 1536
        }
        if (t < KT) ms[t] = mask[rowbase + j0 + t];
        __syncthreads();

        for (int j = 0; j < KT; j++) {
            if (ms[j] == 0) {                 // warp-uniform branch; masked keys skipped
                float s = 0.f;
                #pragma unroll
                for (int c4 = 0; c4 < 16; c4++) {
                    float4 kv = Ks[j * 16 + c4];
                    s += q[c4 * 4 + 0] * kv.x + q[c4 * 4 + 1] * kv.y
                       + q[c4 * 4 + 2] * kv.z + q[c4 * 4 + 3] * kv.w;
                }
                float p = __expf(s);
                l += p;
                #pragma unroll
                for (int c4 = 0; c4 < 16; c4++) {
                    float4 vv = Vs[j * 16 + c4];
                    acc[c4 * 4 + 0] += p * vv.x;
                    acc[c4 * 4 + 1] += p * vv.y;
                    acc[c4 * 4 + 2] += p * vv.z;
                    acc[c4 * 4 + 3] += p * vv.w;
                }
            }
        }
    }

    const float inv = 1.0f / l;

    // Stage normalized output through smem for coalesced global writes
    __syncthreads();
    #pragma unroll
    for (int c4 = 0; c4 < 16; c4++) {
        sbuf[t * 16 + c4] = make_float4(acc[c4 * 4 + 0] * inv, acc[c4 * 4 + 1] * inv,
                                        acc[c4 * 4 + 2] * inv, acc[c4 * 4 + 3] * inv);
    }
    __syncthreads();
    #pragma unroll
    for (int i = 0; i < 16; i++) {
        int idx = i * 128 + t;
        int row = idx >> 4, c4 = idx & 15;
        *(float4*)&out[(rowbase + q0 + row) * CC + h * DH + c4 * 4] = sbuf[idx];
    }
}

// ---------------------------------------------------------------------------
extern "C" void kernel_launch(void* const* d_in, const int* in_sizes, int n_in,
                              void* d_out, int out_size)
{
    const float* x      = (const float*)d_in[0];   // (8,1024,768)
    const int*   mask   = (const int*)  d_in[1];   // (8,1024)
    const float* w_qkv  = (const float*)d_in[2];   // (768,2304)
    const float* w_proj = (const float*)d_in[3];   // (768,768)
    const float* b_proj = (const float*)d_in[4];   // (768,)
    float* out = (float*)d_out;                    // (8,1024,768)

    void *p_qkv = nullptr, *p_att = nullptr;
    cudaGetSymbolAddress(&p_qkv, g_qkv);
    cudaGetSymbolAddress(&p_att, g_att);
    float* qkv = (float*)p_qkv;
    float* att = (float*)p_att;

    // 1) QKV GEMM: (8192,768) @ (768,2304)
    {
        dim3 grid(CQKV / 128, MROWS / 128);
        sgemm128<<<grid, 256>>>(x, w_qkv, nullptr, qkv, MROWS, CQKV, CC);
    }
    // 2) Attention
    {
        dim3 grid(NN / 128, HH, BB);
        attn_kernel<<<grid, 128>>>(qkv, mask, att);
    }
    // 3) Output projection + bias: (8192,768) @ (768,768) + b
    {
        dim3 grid(CC / 128, MROWS / 128);
        sgemm128<<<grid, 256>>>(att, w_proj, b_proj, out, MROWS, CC, CC);
    }
}